// round 11
// baseline (speedup 1.0000x reference)
#include <cuda_runtime.h>
#include <cuda_bf16.h>
#include <cstdint>

// Problem constants
#define Bd 4
#define Cd 256
#define Hd 8
#define NPIX 16384

// f32 intermediates
__device__ float g_Q[NPIX*Cd];
__device__ float g_K[NPIX*Cd];
__device__ float g_V[NPIX*Cd];

// split-bf16 operands
__device__ unsigned short g_Xhi[NPIX*Cd];
__device__ unsigned short g_Xlo[NPIX*Cd];
__device__ unsigned short g_AThi[NPIX*Cd];
__device__ unsigned short g_ATlo[NPIX*Cd];
__device__ unsigned short g_Wthi[4*Cd*Cd];     // W^T  [mat][n][k]
__device__ unsigned short g_Wtlo[4*Cd*Cd];

// ---------------------------------------------------------------------------
__device__ __forceinline__ void split1(float f, unsigned short& h, unsigned short& l) {
    __nv_bfloat16 hb = __float2bfloat16_rn(f);
    __nv_bfloat16 lb = __float2bfloat16_rn(f - __bfloat162float(hb));
    h = __bfloat16_as_ushort(hb);
    l = __bfloat16_as_ushort(lb);
}

__global__ void prep_x_kernel(const float* __restrict__ X)
{
    int g = blockIdx.x * blockDim.x + threadIdx.x;
    int e = g << 2;
    const float4 v = *(const float4*)(X + e);
    ushort4 h, l;
    split1(v.x, h.x, l.x); split1(v.y, h.y, l.y);
    split1(v.z, h.z, l.z); split1(v.w, h.w, l.w);
    *(ushort4*)(g_Xhi + e) = h;
    *(ushort4*)(g_Xlo + e) = l;
}

__global__ void prep_w_kernel(const float* __restrict__ Wq,
                              const float* __restrict__ Wk,
                              const float* __restrict__ Wv,
                              const float* __restrict__ Wo)
{
    int g = blockIdx.x * blockDim.x + threadIdx.x;   // 4*256*64
    int mat = g >> 14;
    int rem = g & 16383;
    int n   = rem >> 6;
    int k0  = (rem & 63) << 2;
    const float* W = (mat == 0) ? Wq : (mat == 1) ? Wk : (mat == 2) ? Wv : Wo;
    ushort4 h, l;
    split1(W[(size_t)(k0 + 0) * 256 + n], h.x, l.x);
    split1(W[(size_t)(k0 + 1) * 256 + n], h.y, l.y);
    split1(W[(size_t)(k0 + 2) * 256 + n], h.z, l.z);
    split1(W[(size_t)(k0 + 3) * 256 + n], h.w, l.w);
    int base = (((mat << 8) | n) << 8) + k0;
    *(ushort4*)(g_Wthi + base) = h;
    *(ushort4*)(g_Wtlo + base) = l;
}

// ---------------------------------------------------------------------------
// bf16 mma.sync GEMM, K'=768 split trick, K=32 per stage (24 stages).
// CTA 128x64, 256 threads (8 warps, 4m x 2n), warp tile 32x32.
// smem rows: 40 bf16 (20 words) -> conflict-free fragment loads.
// ---------------------------------------------------------------------------
#define BM 128
#define BN 64
#define SSTR 40

__device__ __forceinline__ void mma16816(float c[4], const unsigned a[4], const unsigned b[2]) {
    asm volatile(
        "mma.sync.aligned.m16n8k16.row.col.f32.bf16.bf16.f32 "
        "{%0,%1,%2,%3}, {%4,%5,%6,%7}, {%8,%9}, {%0,%1,%2,%3};"
        : "+f"(c[0]), "+f"(c[1]), "+f"(c[2]), "+f"(c[3])
        : "r"(a[0]), "r"(a[1]), "r"(a[2]), "r"(a[3]), "r"(b[0]), "r"(b[1]));
}

__device__ __forceinline__ void mma_gemm(const unsigned short* __restrict__ Ahi,
                                         const unsigned short* __restrict__ Alo,
                                         const unsigned short* __restrict__ Bhi,
                                         const unsigned short* __restrict__ Blo,
                                         float* __restrict__ C,
                                         const float* __restrict__ pos,
                                         bool addpos)
{
    __shared__ unsigned short As[2][BM * SSTR];
    __shared__ unsigned short Bs[2][BN * SSTR];

    const int t    = threadIdx.x;
    const int m0   = blockIdx.y * BM;
    const int n0   = blockIdx.x * BN;
    const int wid  = t >> 5;
    const int lane = t & 31;
    const int grp  = lane >> 2;
    const int tig  = lane & 3;
    const int wm0  = (wid >> 1) << 5;
    const int wn0  = (wid & 1) << 5;

    const int arow = t >> 1;           // 0..127
    const int aseg = (t & 1) << 4;     // 0 / 16
    const int brow = t >> 2;           // 0..63
    const int bseg = (t & 3) << 3;     // 0,8,16,24

    uint4 ra0, ra1, rb;
    auto ldg = [&](int stage) {
        const int ph = stage >> 3;
        const int kk = (stage & 7) << 5;
        const unsigned short* Asrc = (ph < 2) ? Ahi : Alo;
        const unsigned short* Bsrc = (ph == 1) ? Blo : Bhi;
        const unsigned short* ap = Asrc + (size_t)(m0 + arow) * 256 + kk + aseg;
        ra0 = *(const uint4*)(ap);
        ra1 = *(const uint4*)(ap + 8);
        rb  = *(const uint4*)(Bsrc + (size_t)(n0 + brow) * 256 + kk + bseg);
    };
    auto sts = [&](int buf) {
        *(uint4*)(&As[buf][arow * SSTR + aseg])     = ra0;
        *(uint4*)(&As[buf][arow * SSTR + aseg + 8]) = ra1;
        *(uint4*)(&Bs[buf][brow * SSTR + bseg])     = rb;
    };

    float acc[2][4][4];
#pragma unroll
    for (int mi = 0; mi < 2; mi++)
#pragma unroll
        for (int ni = 0; ni < 4; ni++)
#pragma unroll
            for (int j = 0; j < 4; j++) acc[mi][ni][j] = 0.f;

    ldg(0); sts(0); __syncthreads();

    for (int stage = 0; stage < 24; stage++) {
        const int buf = stage & 1;
        const bool more = (stage < 23);
        if (more) ldg(stage + 1);

        const unsigned* As32 = (const unsigned*)&As[buf][0];
        const unsigned* Bs32 = (const unsigned*)&Bs[buf][0];
        unsigned au[2][2][4], bu[4][2][2];
#pragma unroll
        for (int kq = 0; kq < 2; kq++) {
            const int wq = kq << 3;
#pragma unroll
            for (int mi = 0; mi < 2; mi++) {
                const int r0 = wm0 + mi * 16 + grp;
                au[mi][kq][0] = As32[r0 * 20 + wq + tig];
                au[mi][kq][1] = As32[(r0 + 8) * 20 + wq + tig];
                au[mi][kq][2] = As32[r0 * 20 + wq + tig + 4];
                au[mi][kq][3] = As32[(r0 + 8) * 20 + wq + tig + 4];
            }
#pragma unroll
            for (int ni = 0; ni < 4; ni++) {
                const int c0 = wn0 + ni * 8 + grp;
                bu[ni][kq][0] = Bs32[c0 * 20 + wq + tig];
                bu[ni][kq][1] = Bs32[c0 * 20 + wq + tig + 4];
            }
        }
#pragma unroll
        for (int kq = 0; kq < 2; kq++)
#pragma unroll
            for (int mi = 0; mi < 2; mi++)
#pragma unroll
                for (int ni = 0; ni < 4; ni++)
                    mma16816(acc[mi][ni], au[mi][kq], bu[ni][kq]);

        if (more) { sts(buf ^ 1); __syncthreads(); }
    }

#pragma unroll
    for (int mi = 0; mi < 2; mi++) {
#pragma unroll
        for (int half = 0; half < 2; half++) {
            const int m = m0 + wm0 + mi * 16 + grp + half * 8;
            const float* pe = nullptr;
            if (addpos) {
                int y  = (m >> 6) & 63;
                int x  = m & 63;
                int qy = y - min(max(y, 3), 60) + 3;
                int qx = x - min(max(x, 3), 60) + 3;
                pe = pos + (size_t)(qy * 7 + qx) * 256;
            }
#pragma unroll
            for (int ni = 0; ni < 4; ni++) {
                const int n = n0 + wn0 + ni * 8 + tig * 2;
                float2 v = make_float2(acc[mi][ni][half * 2], acc[mi][ni][half * 2 + 1]);
                if (addpos) {
                    const float2 p = *(const float2*)(pe + n);
                    v.x += p.x; v.y += p.y;
                }
                *(float2*)(C + (size_t)m * 256 + n) = v;
            }
        }
    }
}

__global__ __launch_bounds__(256) void qkv_kernel(const float* __restrict__ pos)
{
    const int mat = blockIdx.z;
    float* C = (mat == 0) ? g_Q : (mat == 1) ? g_K : g_V;
    mma_gemm(g_Xhi, g_Xlo,
             g_Wthi + (size_t)mat * 65536, g_Wtlo + (size_t)mat * 65536,
             C, pos, mat == 0);
}

__global__ __launch_bounds__(256) void out_kernel(float* __restrict__ out)
{
    mma_gemm(g_AThi, g_ATlo,
             g_Wthi + (size_t)3 * 65536, g_Wtlo + (size_t)3 * 65536,
             out, nullptr, false);
}

// ---------------------------------------------------------------------------
// Attention: two-phase; exp weights parked in smem between phases (no spills).
// ---------------------------------------------------------------------------
#define TW 16
#define TH 8
#define HW 22
#define NR (HW*14)   // 308

__global__ __launch_bounds__(128, 3) void attn_kernel(const float* __restrict__ pos)
{
    extern __shared__ float smf[];
    float4* KV  = (float4*)smf;          // [8][NR]  (K then V)
    float4* Ps4 = KV + 8 * NR;           // [8][49]
    float*  SCs = (float*)(Ps4 + 8 * 49);// [49][128] exp weights

    const int bx = blockIdx.x;
    const int h  = blockIdx.y;
    const int b  = blockIdx.z;
    const int Ty = (bx >> 2) * TH;
    const int Tx = (bx & 3) * TW;
    const int t  = threadIdx.x;
    const int hb = h * 32;

    for (int i = t; i < NR * 8; i += 128) {
        int r  = i >> 3;
        int f4 = i & 7;
        int ry = r / HW;
        int rx = r - ry * HW;
        int gy = min(max(Ty - 3 + ry, 0), 63);
        int gx = min(max(Tx - 3 + rx, 0), 63);
        size_t off = ((size_t)(((b << 6) + gy) << 6) + gx) * 256 + hb + (f4 << 2);
        KV[f4 * NR + r] = *(const float4*)(g_K + off);
    }
    for (int i = t; i < 49 * 8; i += 128) {
        int s  = i >> 3;
        int f4 = i & 7;
        Ps4[f4 * 49 + s] = *(const float4*)(pos + (size_t)s * 256 + hb + (f4 << 2));
    }
    __syncthreads();

    const int py = t >> 4, px = t & 15;
    const int gy = Ty + py, gx = Tx + px;
    const int pr0 = min(max(gy, 3), 60) - Ty;
    const int pc0 = min(max(gx, 3), 60) - Tx;
    const size_t gp = ((size_t)(((b << 6) + gy) << 6) + gx) * 256 + hb;

    const float scale = 0.17677669529663687f;  // 1/sqrt(32)
    float4 q[8];
#pragma unroll
    for (int f4 = 0; f4 < 8; f4++) {
        float4 v = *(const float4*)(g_Q + gp + (f4 << 2));
        v.x *= scale; v.y *= scale; v.z *= scale; v.w *= scale;
        q[f4] = v;
    }

    // ---- Phase 1: scores -> exp -> smem ----
    float l = 0.f;
#pragma unroll
    for (int dy = 0; dy < 7; dy++) {
        const int r0 = (pr0 + dy) * HW + pc0;
        const int s0 = dy * 7;
#pragma unroll
        for (int dx = 0; dx < 7; dx++) {
            const int r = r0 + dx;
            const int s = s0 + dx;
            float4 d = make_float4(0.f, 0.f, 0.f, 0.f);
#pragma unroll
            for (int f4 = 0; f4 < 8; f4++) {
                const float4 k = KV[f4 * NR + r];
                const float4 p = Ps4[f4 * 49 + s];
                d.x = fmaf(q[f4].x, k.x + p.x, d.x);
                d.y = fmaf(q[f4].y, k.y + p.y, d.y);
                d.z = fmaf(q[f4].z, k.z + p.z, d.z);
                d.w = fmaf(q[f4].w, k.w + p.w, d.w);
            }
            const float w = __expf((d.x + d.y) + (d.z + d.w));
            l += w;
            SCs[s * 128 + t] = w;
        }
    }
    __syncthreads();

    // ---- Reload buffer with V halo (L2-hot) ----
    for (int i = t; i < NR * 8; i += 128) {
        int r  = i >> 3;
        int f4 = i & 7;
        int ry = r / HW;
        int rx = r - ry * HW;
        int gyv = min(max(Ty - 3 + ry, 0), 63);
        int gxv = min(max(Tx - 3 + rx, 0), 63);
        size_t off = ((size_t)(((b << 6) + gyv) << 6) + gxv) * 256 + hb + (f4 << 2);
        KV[f4 * NR + r] = *(const float4*)(g_V + off);
    }
    __syncthreads();

    // ---- Phase 2: weighted V accumulate ----
    float4 acc[8];
#pragma unroll
    for (int f4 = 0; f4 < 8; f4++) acc[f4] = make_float4(0.f, 0.f, 0.f, 0.f);

#pragma unroll
    for (int dy = 0; dy < 7; dy++) {
        const int r0 = (pr0 + dy) * HW + pc0;
        const int s0 = dy * 7;
#pragma unroll
        for (int dx = 0; dx < 7; dx++) {
            const int r = r0 + dx;
            const float w = SCs[(s0 + dx) * 128 + t];
#pragma unroll
            for (int f4 = 0; f4 < 8; f4++) {
                const float4 v = KV[f4 * NR + r];
                acc[f4].x = fmaf(w, v.x, acc[f4].x);
                acc[f4].y = fmaf(w, v.y, acc[f4].y);
                acc[f4].z = fmaf(w, v.z, acc[f4].z);
                acc[f4].w = fmaf(w, v.w, acc[f4].w);
            }
        }
    }

    const float inv = __fdividef(1.f, l + 1e-8f);
#pragma unroll
    for (int f4 = 0; f4 < 8; f4++) {
        float o[4] = {acc[f4].x * inv, acc[f4].y * inv, acc[f4].z * inv, acc[f4].w * inv};
        ushort4 hv, lv;
        split1(o[0], hv.x, lv.x); split1(o[1], hv.y, lv.y);
        split1(o[2], hv.z, lv.z); split1(o[3], hv.w, lv.w);
        *(ushort4*)(g_AThi + gp + (f4 << 2)) = hv;
        *(ushort4*)(g_ATlo + gp + (f4 << 2)) = lv;
    }
}

// ---------------------------------------------------------------------------
extern "C" void kernel_launch(void* const* d_in, const int* in_sizes, int n_in,
                              void* d_out, int out_size)
{
    const float* x   = (const float*)d_in[0];
    const float* Wq  = (const float*)d_in[1];
    const float* Wk  = (const float*)d_in[2];
    const float* Wv  = (const float*)d_in[3];
    const float* Wo  = (const float*)d_in[4];
    const float* pos = (const float*)d_in[5];

    prep_w_kernel<<<256, 256>>>(Wq, Wk, Wv, Wo);
    prep_x_kernel<<<4096, 256>>>(x);

    qkv_kernel<<<dim3(Cd / BN, NPIX / BM, 3), 256>>>(pos);

    const int smem = (8 * NR + 8 * 49) * (int)sizeof(float4) + 49 * 128 * (int)sizeof(float);
    cudaFuncSetAttribute(attn_kernel, cudaFuncAttributeMaxDynamicSharedMemorySize, smem);
    attn_kernel<<<dim3(32, Hd, Bd), 128, smem>>>(pos);

    out_kernel<<<dim3(Cd / BN, NPIX / BM, 1), 256>>>((float*)d_out);
}

// round 12
// speedup vs baseline: 1.0503x; 1.0503x over previous
#include <cuda_runtime.h>
#include <cuda_bf16.h>
#include <cstdint>

// Problem constants
#define Bd 4
#define Cd 256
#define Hd 8
#define NPIX 16384

// f32 intermediates
__device__ float g_Q[NPIX*Cd];
__device__ float g_K[NPIX*Cd];
__device__ float g_V[NPIX*Cd];

// split-bf16 operands
__device__ unsigned short g_Xhi[NPIX*Cd];
__device__ unsigned short g_Xlo[NPIX*Cd];
__device__ unsigned short g_AThi[NPIX*Cd];
__device__ unsigned short g_ATlo[NPIX*Cd];
__device__ unsigned short g_Wthi[4*Cd*Cd];     // W^T  [mat][n][k]
__device__ unsigned short g_Wtlo[4*Cd*Cd];

// ---------------------------------------------------------------------------
__device__ __forceinline__ void split1(float f, unsigned short& h, unsigned short& l) {
    __nv_bfloat16 hb = __float2bfloat16_rn(f);
    __nv_bfloat16 lb = __float2bfloat16_rn(f - __bfloat162float(hb));
    h = __bfloat16_as_ushort(hb);
    l = __bfloat16_as_ushort(lb);
}

__global__ void prep_x_kernel(const float* __restrict__ X)
{
    int g = blockIdx.x * blockDim.x + threadIdx.x;
    int e = g << 2;
    const float4 v = *(const float4*)(X + e);
    ushort4 h, l;
    split1(v.x, h.x, l.x); split1(v.y, h.y, l.y);
    split1(v.z, h.z, l.z); split1(v.w, h.w, l.w);
    *(ushort4*)(g_Xhi + e) = h;
    *(ushort4*)(g_Xlo + e) = l;
}

__global__ void prep_w_kernel(const float* __restrict__ Wq,
                              const float* __restrict__ Wk,
                              const float* __restrict__ Wv,
                              const float* __restrict__ Wo)
{
    int g = blockIdx.x * blockDim.x + threadIdx.x;   // 4*256*64
    int mat = g >> 14;
    int rem = g & 16383;
    int n   = rem >> 6;
    int k0  = (rem & 63) << 2;
    const float* W = (mat == 0) ? Wq : (mat == 1) ? Wk : (mat == 2) ? Wv : Wo;
    ushort4 h, l;
    split1(W[(size_t)(k0 + 0) * 256 + n], h.x, l.x);
    split1(W[(size_t)(k0 + 1) * 256 + n], h.y, l.y);
    split1(W[(size_t)(k0 + 2) * 256 + n], h.z, l.z);
    split1(W[(size_t)(k0 + 3) * 256 + n], h.w, l.w);
    int base = (((mat << 8) | n) << 8) + k0;
    *(ushort4*)(g_Wthi + base) = h;
    *(ushort4*)(g_Wtlo + base) = l;
}

// ---------------------------------------------------------------------------
// bf16 mma.sync GEMM, K'=768 split trick, K=32 per stage (24 stages).
// CTA 128x64, 256 threads (8 warps, 4m x 2n), warp tile 32x32.
// ---------------------------------------------------------------------------
#define BM 128
#define BN 64
#define SSTR 40

__device__ __forceinline__ void mma16816(float c[4], const unsigned a[4], const unsigned b[2]) {
    asm volatile(
        "mma.sync.aligned.m16n8k16.row.col.f32.bf16.bf16.f32 "
        "{%0,%1,%2,%3}, {%4,%5,%6,%7}, {%8,%9}, {%0,%1,%2,%3};"
        : "+f"(c[0]), "+f"(c[1]), "+f"(c[2]), "+f"(c[3])
        : "r"(a[0]), "r"(a[1]), "r"(a[2]), "r"(a[3]), "r"(b[0]), "r"(b[1]));
}

__device__ __forceinline__ void mma_gemm(const unsigned short* __restrict__ Ahi,
                                         const unsigned short* __restrict__ Alo,
                                         const unsigned short* __restrict__ Bhi,
                                         const unsigned short* __restrict__ Blo,
                                         float* __restrict__ C,
                                         const float* __restrict__ pos,
                                         bool addpos)
{
    __shared__ unsigned short As[2][BM * SSTR];
    __shared__ unsigned short Bs[2][BN * SSTR];

    const int t    = threadIdx.x;
    const int m0   = blockIdx.y * BM;
    const int n0   = blockIdx.x * BN;
    const int wid  = t >> 5;
    const int lane = t & 31;
    const int grp  = lane >> 2;
    const int tig  = lane & 3;
    const int wm0  = (wid >> 1) << 5;
    const int wn0  = (wid & 1) << 5;

    const int arow = t >> 1;
    const int aseg = (t & 1) << 4;
    const int brow = t >> 2;
    const int bseg = (t & 3) << 3;

    uint4 ra0, ra1, rb;
    auto ldg = [&](int stage) {
        const int ph = stage >> 3;
        const int kk = (stage & 7) << 5;
        const unsigned short* Asrc = (ph < 2) ? Ahi : Alo;
        const unsigned short* Bsrc = (ph == 1) ? Blo : Bhi;
        const unsigned short* ap = Asrc + (size_t)(m0 + arow) * 256 + kk + aseg;
        ra0 = *(const uint4*)(ap);
        ra1 = *(const uint4*)(ap + 8);
        rb  = *(const uint4*)(Bsrc + (size_t)(n0 + brow) * 256 + kk + bseg);
    };
    auto sts = [&](int buf) {
        *(uint4*)(&As[buf][arow * SSTR + aseg])     = ra0;
        *(uint4*)(&As[buf][arow * SSTR + aseg + 8]) = ra1;
        *(uint4*)(&Bs[buf][brow * SSTR + bseg])     = rb;
    };

    float acc[2][4][4];
#pragma unroll
    for (int mi = 0; mi < 2; mi++)
#pragma unroll
        for (int ni = 0; ni < 4; ni++)
#pragma unroll
            for (int j = 0; j < 4; j++) acc[mi][ni][j] = 0.f;

    ldg(0); sts(0); __syncthreads();

    for (int stage = 0; stage < 24; stage++) {
        const int buf = stage & 1;
        const bool more = (stage < 23);
        if (more) ldg(stage + 1);

        const unsigned* As32 = (const unsigned*)&As[buf][0];
        const unsigned* Bs32 = (const unsigned*)&Bs[buf][0];
        unsigned au[2][2][4], bu[4][2][2];
#pragma unroll
        for (int kq = 0; kq < 2; kq++) {
            const int wq = kq << 3;
#pragma unroll
            for (int mi = 0; mi < 2; mi++) {
                const int r0 = wm0 + mi * 16 + grp;
                au[mi][kq][0] = As32[r0 * 20 + wq + tig];
                au[mi][kq][1] = As32[(r0 + 8) * 20 + wq + tig];
                au[mi][kq][2] = As32[r0 * 20 + wq + tig + 4];
                au[mi][kq][3] = As32[(r0 + 8) * 20 + wq + tig + 4];
            }
#pragma unroll
            for (int ni = 0; ni < 4; ni++) {
                const int c0 = wn0 + ni * 8 + grp;
                bu[ni][kq][0] = Bs32[c0 * 20 + wq + tig];
                bu[ni][kq][1] = Bs32[c0 * 20 + wq + tig + 4];
            }
        }
#pragma unroll
        for (int kq = 0; kq < 2; kq++)
#pragma unroll
            for (int mi = 0; mi < 2; mi++)
#pragma unroll
                for (int ni = 0; ni < 4; ni++)
                    mma16816(acc[mi][ni], au[mi][kq], bu[ni][kq]);

        if (more) { sts(buf ^ 1); __syncthreads(); }
    }

#pragma unroll
    for (int mi = 0; mi < 2; mi++) {
#pragma unroll
        for (int half = 0; half < 2; half++) {
            const int m = m0 + wm0 + mi * 16 + grp + half * 8;
            const float* pe = nullptr;
            if (addpos) {
                int y  = (m >> 6) & 63;
                int x  = m & 63;
                int qy = y - min(max(y, 3), 60) + 3;
                int qx = x - min(max(x, 3), 60) + 3;
                pe = pos + (size_t)(qy * 7 + qx) * 256;
            }
#pragma unroll
            for (int ni = 0; ni < 4; ni++) {
                const int n = n0 + wn0 + ni * 8 + tig * 2;
                float2 v = make_float2(acc[mi][ni][half * 2], acc[mi][ni][half * 2 + 1]);
                if (addpos) {
                    const float2 p = *(const float2*)(pe + n);
                    v.x += p.x; v.y += p.y;
                }
                *(float2*)(C + (size_t)m * 256 + n) = v;
            }
        }
    }
}

__global__ __launch_bounds__(256) void qkv_kernel(const float* __restrict__ pos)
{
    const int mat = blockIdx.z;
    float* C = (mat == 0) ? g_Q : (mat == 1) ? g_K : g_V;
    mma_gemm(g_Xhi, g_Xlo,
             g_Wthi + (size_t)mat * 65536, g_Wtlo + (size_t)mat * 65536,
             C, pos, mat == 0);
}

__global__ __launch_bounds__(256) void out_kernel(float* __restrict__ out)
{
    mma_gemm(g_AThi, g_ATlo,
             g_Wthi + (size_t)3 * 65536, g_Wtlo + (size_t)3 * 65536,
             out, nullptr, false);
}

// ---------------------------------------------------------------------------
// Attention: lane-pair feature split. 256 threads, pixel = (warp,lane&15),
// half = lane>>4. Score partials combined with shfl_xor(16); w in smem.
// Two-phase single K/V buffer. regs ~64 -> 3 blocks/SM, 24 warps.
// ---------------------------------------------------------------------------
#define TW 16
#define TH 8
#define HW 22
#define NR (HW*14)   // 308

__global__ __launch_bounds__(256, 3) void attn_kernel(const float* __restrict__ pos)
{
    extern __shared__ float smf[];
    float4* KV  = (float4*)smf;            // [8][NR]  (K then V)
    float4* Ps4 = KV + 8 * NR;             // [8][49]
    float*  SCs = (float*)(Ps4 + 8 * 49);  // [49][128] exp weights

    const int bx = blockIdx.x;
    const int h  = blockIdx.y;
    const int b  = blockIdx.z;
    const int Ty = (bx >> 2) * TH;
    const int Tx = (bx & 3) * TW;
    const int t  = threadIdx.x;
    const int hb = h * 32;

    // ---- Load K halo + P ----
    for (int i = t; i < NR * 8; i += 256) {
        int r  = i >> 3;
        int f4 = i & 7;
        int ry = r / HW;
        int rx = r - ry * HW;
        int gy = min(max(Ty - 3 + ry, 0), 63);
        int gx = min(max(Tx - 3 + rx, 0), 63);
        size_t off = ((size_t)(((b << 6) + gy) << 6) + gx) * 256 + hb + (f4 << 2);
        KV[f4 * NR + r] = *(const float4*)(g_K + off);
    }
    for (int i = t; i < 49 * 8; i += 256) {
        int s  = i >> 3;
        int f4 = i & 7;
        Ps4[f4 * 49 + s] = *(const float4*)(pos + (size_t)s * 256 + hb + (f4 << 2));
    }
    __syncthreads();

    const int warp = t >> 5;
    const int lane = t & 31;
    const int half = lane >> 4;            // 0/1: feature half
    const int pix  = (warp << 4) + (lane & 15);   // 0..127
    const int f4b  = half << 2;            // plane base: 0 or 4

    const int py = pix >> 4, px = pix & 15;
    const int gy = Ty + py, gx = Tx + px;
    const int pr0 = min(max(gy, 3), 60) - Ty;
    const int pc0 = min(max(gx, 3), 60) - Tx;
    const size_t gp = ((size_t)(((b << 6) + gy) << 6) + gx) * 256 + hb;

    const float scale = 0.17677669529663687f;  // 1/sqrt(32)
    float4 q[4];
#pragma unroll
    for (int j = 0; j < 4; j++) {
        float4 v = *(const float4*)(g_Q + gp + ((f4b + j) << 2));
        v.x *= scale; v.y *= scale; v.z *= scale; v.w *= scale;
        q[j] = v;
    }

    // ---- Phase 1: scores -> shfl-combine -> exp -> smem ----
    float l = 0.f;
#pragma unroll
    for (int dy = 0; dy < 7; dy++) {
        const int r0 = (pr0 + dy) * HW + pc0;
        const int s0 = dy * 7;
#pragma unroll
        for (int dx = 0; dx < 7; dx++) {
            const int r = r0 + dx;
            const int s = s0 + dx;
            float4 d = make_float4(0.f, 0.f, 0.f, 0.f);
#pragma unroll
            for (int j = 0; j < 4; j++) {
                const float4 k = KV[(f4b + j) * NR + r];
                const float4 p = Ps4[(f4b + j) * 49 + s];
                d.x = fmaf(q[j].x, k.x + p.x, d.x);
                d.y = fmaf(q[j].y, k.y + p.y, d.y);
                d.z = fmaf(q[j].z, k.z + p.z, d.z);
                d.w = fmaf(q[j].w, k.w + p.w, d.w);
            }
            float part = (d.x + d.y) + (d.z + d.w);
            part += __shfl_xor_sync(0xffffffffu, part, 16);
            const float w = __expf(part);
            l += w;
            if (half == 0) SCs[s * 128 + pix] = w;
        }
    }
    __syncthreads();

    // ---- Reload buffer with V halo (L2-hot) ----
    for (int i = t; i < NR * 8; i += 256) {
        int r  = i >> 3;
        int f4 = i & 7;
        int ry = r / HW;
        int rx = r - ry * HW;
        int gyv = min(max(Ty - 3 + ry, 0), 63);
        int gxv = min(max(Tx - 3 + rx, 0), 63);
        size_t off = ((size_t)(((b << 6) + gyv) << 6) + gxv) * 256 + hb + (f4 << 2);
        KV[f4 * NR + r] = *(const float4*)(g_V + off);
    }
    __syncthreads();

    // ---- Phase 2: weighted V accumulate (my 16 features) ----
    float4 acc[4];
#pragma unroll
    for (int j = 0; j < 4; j++) acc[j] = make_float4(0.f, 0.f, 0.f, 0.f);

#pragma unroll
    for (int dy = 0; dy < 7; dy++) {
        const int r0 = (pr0 + dy) * HW + pc0;
        const int s0 = dy * 7;
#pragma unroll
        for (int dx = 0; dx < 7; dx++) {
            const int r = r0 + dx;
            const float w = SCs[(s0 + dx) * 128 + pix];
#pragma unroll
            for (int j = 0; j < 4; j++) {
                const float4 v = KV[(f4b + j) * NR + r];
                acc[j].x = fmaf(w, v.x, acc[j].x);
                acc[j].y = fmaf(w, v.y, acc[j].y);
                acc[j].z = fmaf(w, v.z, acc[j].z);
                acc[j].w = fmaf(w, v.w, acc[j].w);
            }
        }
    }

    const float inv = __fdividef(1.f, l + 1e-8f);
#pragma unroll
    for (int j = 0; j < 4; j++) {
        float o[4] = {acc[j].x * inv, acc[j].y * inv, acc[j].z * inv, acc[j].w * inv};
        ushort4 hv, lv;
        split1(o[0], hv.x, lv.x); split1(o[1], hv.y, lv.y);
        split1(o[2], hv.z, lv.z); split1(o[3], hv.w, lv.w);
        *(ushort4*)(g_AThi + gp + ((f4b + j) << 2)) = hv;
        *(ushort4*)(g_ATlo + gp + ((f4b + j) << 2)) = lv;
    }
}

// ---------------------------------------------------------------------------
extern "C" void kernel_launch(void* const* d_in, const int* in_sizes, int n_in,
                              void* d_out, int out_size)
{
    const float* x   = (const float*)d_in[0];
    const float* Wq  = (const float*)d_in[1];
    const float* Wk  = (const float*)d_in[2];
    const float* Wv  = (const float*)d_in[3];
    const float* Wo  = (const float*)d_in[4];
    const float* pos = (const float*)d_in[5];

    prep_w_kernel<<<256, 256>>>(Wq, Wk, Wv, Wo);
    prep_x_kernel<<<4096, 256>>>(x);

    qkv_kernel<<<dim3(Cd / BN, NPIX / BM, 3), 256>>>(pos);

    const int smem = (8 * NR + 8 * 49) * (int)sizeof(float4) + 49 * 128 * (int)sizeof(float);
    cudaFuncSetAttribute(attn_kernel, cudaFuncAttributeMaxDynamicSharedMemorySize, smem);
    attn_kernel<<<dim3(32, Hd, Bd), 256, smem>>>(pos);

    out_kernel<<<dim3(Cd / BN, NPIX / BM, 1), 256>>>((float*)d_out);
}

// round 13
// speedup vs baseline: 1.0672x; 1.0161x over previous
#include <cuda_runtime.h>
#include <cuda_bf16.h>
#include <cstdint>

// Problem constants
#define Bd 4
#define Cd 256
#define Hd 8
#define NPIX 16384

// f32 intermediates
__device__ float g_Q[NPIX*Cd];
__device__ float g_K[NPIX*Cd];
__device__ float g_V[NPIX*Cd];

// split-bf16 operands
__device__ unsigned short g_Xhi[NPIX*Cd];
__device__ unsigned short g_Xlo[NPIX*Cd];
__device__ unsigned short g_AThi[NPIX*Cd];
__device__ unsigned short g_ATlo[NPIX*Cd];
__device__ unsigned short g_Wthi[4*Cd*Cd];     // W^T  [mat][n][k]
__device__ unsigned short g_Wtlo[4*Cd*Cd];

// ---------------------------------------------------------------------------
__device__ __forceinline__ void split1(float f, unsigned short& h, unsigned short& l) {
    __nv_bfloat16 hb = __float2bfloat16_rn(f);
    __nv_bfloat16 lb = __float2bfloat16_rn(f - __bfloat162float(hb));
    h = __bfloat16_as_ushort(hb);
    l = __bfloat16_as_ushort(lb);
}

__global__ void prep_x_kernel(const float* __restrict__ X)
{
    int g = blockIdx.x * blockDim.x + threadIdx.x;
    int e = g << 2;
    const float4 v = *(const float4*)(X + e);
    ushort4 h, l;
    split1(v.x, h.x, l.x); split1(v.y, h.y, l.y);
    split1(v.z, h.z, l.z); split1(v.w, h.w, l.w);
    *(ushort4*)(g_Xhi + e) = h;
    *(ushort4*)(g_Xlo + e) = l;
}

__global__ void prep_w_kernel(const float* __restrict__ Wq,
                              const float* __restrict__ Wk,
                              const float* __restrict__ Wv,
                              const float* __restrict__ Wo)
{
    int g = blockIdx.x * blockDim.x + threadIdx.x;   // 4*256*64
    int mat = g >> 14;
    int rem = g & 16383;
    int n   = rem >> 6;
    int k0  = (rem & 63) << 2;
    const float* W = (mat == 0) ? Wq : (mat == 1) ? Wk : (mat == 2) ? Wv : Wo;
    ushort4 h, l;
    split1(W[(size_t)(k0 + 0) * 256 + n], h.x, l.x);
    split1(W[(size_t)(k0 + 1) * 256 + n], h.y, l.y);
    split1(W[(size_t)(k0 + 2) * 256 + n], h.z, l.z);
    split1(W[(size_t)(k0 + 3) * 256 + n], h.w, l.w);
    int base = (((mat << 8) | n) << 8) + k0;
    *(ushort4*)(g_Wthi + base) = h;
    *(ushort4*)(g_Wtlo + base) = l;
}

// ---------------------------------------------------------------------------
// bf16 mma.sync GEMM, K'=768 split trick, K=32 per stage (24 stages).
// Fragments via ldmatrix.x4 (identical lane layout to prior scalar loads).
// ---------------------------------------------------------------------------
#define BM 128
#define BN 64
#define SSTR 40

__device__ __forceinline__ uint32_t smem_u32(const void* p) {
    uint32_t a;
    asm("{ .reg .u64 t; cvta.to.shared.u64 t, %1; cvt.u32.u64 %0, t; }" : "=r"(a) : "l"(p));
    return a;
}
__device__ __forceinline__ void ldsm_x4(uint32_t addr, unsigned& r0, unsigned& r1,
                                        unsigned& r2, unsigned& r3) {
    asm volatile("ldmatrix.sync.aligned.m8n8.x4.shared.b16 {%0,%1,%2,%3}, [%4];"
                 : "=r"(r0), "=r"(r1), "=r"(r2), "=r"(r3) : "r"(addr));
}
__device__ __forceinline__ void mma16816(float c[4], const unsigned a[4], const unsigned b[2]) {
    asm volatile(
        "mma.sync.aligned.m16n8k16.row.col.f32.bf16.bf16.f32 "
        "{%0,%1,%2,%3}, {%4,%5,%6,%7}, {%8,%9}, {%0,%1,%2,%3};"
        : "+f"(c[0]), "+f"(c[1]), "+f"(c[2]), "+f"(c[3])
        : "r"(a[0]), "r"(a[1]), "r"(a[2]), "r"(a[3]), "r"(b[0]), "r"(b[1]));
}

__device__ __forceinline__ void mma_gemm(const unsigned short* __restrict__ Ahi,
                                         const unsigned short* __restrict__ Alo,
                                         const unsigned short* __restrict__ Bhi,
                                         const unsigned short* __restrict__ Blo,
                                         float* __restrict__ C,
                                         const float* __restrict__ pos,
                                         bool addpos)
{
    __shared__ unsigned short As[2][BM * SSTR];
    __shared__ unsigned short Bs[2][BN * SSTR];

    const int t    = threadIdx.x;
    const int m0   = blockIdx.y * BM;
    const int n0   = blockIdx.x * BN;
    const int wid  = t >> 5;
    const int lane = t & 31;
    const int grp  = lane >> 2;
    const int tig  = lane & 3;
    const int wm0  = (wid >> 1) << 5;
    const int wn0  = (wid & 1) << 5;

    const int arow = t >> 1;
    const int aseg = (t & 1) << 4;
    const int brow = t >> 2;
    const int bseg = (t & 3) << 3;

    // ldmatrix lane address components
    const uint32_t asb = smem_u32(&As[0][0]);
    const uint32_t bsb = smem_u32(&Bs[0][0]);
    const int rA = lane & 15;                        // A row within 16-row tile
    const int cA = (lane >> 4) << 3;                 // A col (shorts): 0/8
    const int rB = ((lane >> 4) << 3) + (lane & 7);  // B row within 16-row tile
    const int cB = ((lane >> 3) & 1) << 3;           // B col (shorts): 0/8

    uint4 ra0, ra1, rb;
    auto ldg = [&](int stage) {
        const int ph = stage >> 3;
        const int kk = (stage & 7) << 5;
        const unsigned short* Asrc = (ph < 2) ? Ahi : Alo;
        const unsigned short* Bsrc = (ph == 1) ? Blo : Bhi;
        const unsigned short* ap = Asrc + (size_t)(m0 + arow) * 256 + kk + aseg;
        ra0 = *(const uint4*)(ap);
        ra1 = *(const uint4*)(ap + 8);
        rb  = *(const uint4*)(Bsrc + (size_t)(n0 + brow) * 256 + kk + bseg);
    };
    auto sts = [&](int buf) {
        *(uint4*)(&As[buf][arow * SSTR + aseg])     = ra0;
        *(uint4*)(&As[buf][arow * SSTR + aseg + 8]) = ra1;
        *(uint4*)(&Bs[buf][brow * SSTR + bseg])     = rb;
    };

    float acc[2][4][4];
#pragma unroll
    for (int mi = 0; mi < 2; mi++)
#pragma unroll
        for (int ni = 0; ni < 4; ni++)
#pragma unroll
            for (int j = 0; j < 4; j++) acc[mi][ni][j] = 0.f;

    ldg(0); sts(0); __syncthreads();

    for (int stage = 0; stage < 24; stage++) {
        const int buf = stage & 1;
        const bool more = (stage < 23);
        if (more) ldg(stage + 1);

        const uint32_t aoff = asb + (uint32_t)buf * (BM * SSTR * 2);
        const uint32_t boff = bsb + (uint32_t)buf * (BN * SSTR * 2);
        unsigned au[2][2][4], bu[4][2][2];
#pragma unroll
        for (int kq = 0; kq < 2; kq++) {
#pragma unroll
            for (int mi = 0; mi < 2; mi++) {
                const uint32_t addr = aoff +
                    (uint32_t)(((wm0 + mi * 16 + rA) * SSTR + kq * 16 + cA) * 2);
                ldsm_x4(addr, au[mi][kq][0], au[mi][kq][1], au[mi][kq][2], au[mi][kq][3]);
            }
#pragma unroll
            for (int np = 0; np < 2; np++) {
                const uint32_t addr = boff +
                    (uint32_t)(((wn0 + np * 16 + rB) * SSTR + kq * 16 + cB) * 2);
                ldsm_x4(addr, bu[np * 2][kq][0], bu[np * 2][kq][1],
                              bu[np * 2 + 1][kq][0], bu[np * 2 + 1][kq][1]);
            }
        }
#pragma unroll
        for (int kq = 0; kq < 2; kq++)
#pragma unroll
            for (int mi = 0; mi < 2; mi++)
#pragma unroll
                for (int ni = 0; ni < 4; ni++)
                    mma16816(acc[mi][ni], au[mi][kq], bu[ni][kq]);

        if (more) { sts(buf ^ 1); __syncthreads(); }
    }

#pragma unroll
    for (int mi = 0; mi < 2; mi++) {
#pragma unroll
        for (int half = 0; half < 2; half++) {
            const int m = m0 + wm0 + mi * 16 + grp + half * 8;
            const float* pe = nullptr;
            if (addpos) {
                int y  = (m >> 6) & 63;
                int x  = m & 63;
                int qy = y - min(max(y, 3), 60) + 3;
                int qx = x - min(max(x, 3), 60) + 3;
                pe = pos + (size_t)(qy * 7 + qx) * 256;
            }
#pragma unroll
            for (int ni = 0; ni < 4; ni++) {
                const int n = n0 + wn0 + ni * 8 + tig * 2;
                float2 v = make_float2(acc[mi][ni][half * 2], acc[mi][ni][half * 2 + 1]);
                if (addpos) {
                    const float2 p = *(const float2*)(pe + n);
                    v.x += p.x; v.y += p.y;
                }
                *(float2*)(C + (size_t)m * 256 + n) = v;
            }
        }
    }
}

__global__ __launch_bounds__(256) void qkv_kernel(const float* __restrict__ pos)
{
    const int mat = blockIdx.z;
    float* C = (mat == 0) ? g_Q : (mat == 1) ? g_K : g_V;
    mma_gemm(g_Xhi, g_Xlo,
             g_Wthi + (size_t)mat * 65536, g_Wtlo + (size_t)mat * 65536,
             C, pos, mat == 0);
}

__global__ __launch_bounds__(256) void out_kernel(float* __restrict__ out)
{
    mma_gemm(g_AThi, g_ATlo,
             g_Wthi + (size_t)3 * 65536, g_Wtlo + (size_t)3 * 65536,
             out, nullptr, false);
}

// ---------------------------------------------------------------------------
// Attention: SINGLE PASS, lane-pair feature split, 8x8 tile (halo 14x14).
// K+V+P all resident (56.4KB) -> 4 blocks/SM; no spills (regs ~60-90).
// ---------------------------------------------------------------------------
#define AHW 14
#define ANR (AHW*AHW)   // 196

__global__ __launch_bounds__(128, 4) void attn_kernel(const float* __restrict__ pos)
{
    extern __shared__ float4 sm4[];
    float4* Ks4 = sm4;                  // [8][ANR]
    float4* Vs4 = sm4 + 8 * ANR;        // [8][ANR]
    float4* Ps4 = sm4 + 16 * ANR;       // [8][49]

    const int bx = blockIdx.x;          // 0..63 (8x8 tiles)
    const int h  = blockIdx.y;
    const int b  = blockIdx.z;
    const int Ty = (bx >> 3) << 3;
    const int Tx = (bx & 7) << 3;
    const int t  = threadIdx.x;
    const int hb = h * 32;

    for (int i = t; i < ANR * 8; i += 128) {
        int r  = i >> 3;
        int f4 = i & 7;
        int ry = r / AHW;
        int rx = r - ry * AHW;
        int gy = min(max(Ty - 3 + ry, 0), 63);
        int gx = min(max(Tx - 3 + rx, 0), 63);
        size_t off = ((size_t)(((b << 6) + gy) << 6) + gx) * 256 + hb + (f4 << 2);
        Ks4[f4 * ANR + r] = *(const float4*)(g_K + off);
        Vs4[f4 * ANR + r] = *(const float4*)(g_V + off);
    }
    for (int i = t; i < 49 * 8; i += 128) {
        int s  = i >> 3;
        int f4 = i & 7;
        Ps4[f4 * 49 + s] = *(const float4*)(pos + (size_t)s * 256 + hb + (f4 << 2));
    }
    __syncthreads();

    const int warp = t >> 5;
    const int lane = t & 31;
    const int half = lane >> 4;               // feature half
    const int pix  = (warp << 4) + (lane & 15);  // 0..63
    const int f4b  = half << 2;

    const int py = pix >> 3, px = pix & 7;
    const int gy = Ty + py, gx = Tx + px;
    const int pr0 = min(max(gy, 3), 60) - Ty;
    const int pc0 = min(max(gx, 3), 60) - Tx;
    const size_t gp = ((size_t)(((b << 6) + gy) << 6) + gx) * 256 + hb;

    const float scale = 0.17677669529663687f;  // 1/sqrt(32)
    float4 q[4];
#pragma unroll
    for (int j = 0; j < 4; j++) {
        float4 v = *(const float4*)(g_Q + gp + ((f4b + j) << 2));
        v.x *= scale; v.y *= scale; v.z *= scale; v.w *= scale;
        q[j] = v;
    }

    float l = 0.f;
    float4 acc[4];
#pragma unroll
    for (int j = 0; j < 4; j++) acc[j] = make_float4(0.f, 0.f, 0.f, 0.f);

#pragma unroll 1
    for (int dy = 0; dy < 7; dy++) {
        const int r0 = (pr0 + dy) * AHW + pc0;
        const int s0 = dy * 7;
#pragma unroll
        for (int dx = 0; dx < 7; dx++) {
            const int r = r0 + dx;
            const int s = s0 + dx;
            float4 d = make_float4(0.f, 0.f, 0.f, 0.f);
#pragma unroll
            for (int j = 0; j < 4; j++) {
                const float4 k = Ks4[(f4b + j) * ANR + r];
                const float4 p = Ps4[(f4b + j) * 49 + s];
                d.x = fmaf(q[j].x, k.x + p.x, d.x);
                d.y = fmaf(q[j].y, k.y + p.y, d.y);
                d.z = fmaf(q[j].z, k.z + p.z, d.z);
                d.w = fmaf(q[j].w, k.w + p.w, d.w);
            }
            float part = (d.x + d.y) + (d.z + d.w);
            part += __shfl_xor_sync(0xffffffffu, part, 16);
            const float w = __expf(part);
            l += w;
#pragma unroll
            for (int j = 0; j < 4; j++) {
                const float4 v = Vs4[(f4b + j) * ANR + r];
                acc[j].x = fmaf(w, v.x, acc[j].x);
                acc[j].y = fmaf(w, v.y, acc[j].y);
                acc[j].z = fmaf(w, v.z, acc[j].z);
                acc[j].w = fmaf(w, v.w, acc[j].w);
            }
        }
    }

    const float inv = __fdividef(1.f, l + 1e-8f);
#pragma unroll
    for (int j = 0; j < 4; j++) {
        float o[4] = {acc[j].x * inv, acc[j].y * inv, acc[j].z * inv, acc[j].w * inv};
        ushort4 hv, lv;
        split1(o[0], hv.x, lv.x); split1(o[1], hv.y, lv.y);
        split1(o[2], hv.z, lv.z); split1(o[3], hv.w, lv.w);
        *(ushort4*)(g_AThi + gp + ((f4b + j) << 2)) = hv;
        *(ushort4*)(g_ATlo + gp + ((f4b + j) << 2)) = lv;
    }
}

// ---------------------------------------------------------------------------
extern "C" void kernel_launch(void* const* d_in, const int* in_sizes, int n_in,
                              void* d_out, int out_size)
{
    const float* x   = (const float*)d_in[0];
    const float* Wq  = (const float*)d_in[1];
    const float* Wk  = (const float*)d_in[2];
    const float* Wv  = (const float*)d_in[3];
    const float* Wo  = (const float*)d_in[4];
    const float* pos = (const float*)d_in[5];

    prep_w_kernel<<<256, 256>>>(Wq, Wk, Wv, Wo);
    prep_x_kernel<<<4096, 256>>>(x);

    qkv_kernel<<<dim3(Cd / BN, NPIX / BM, 3), 256>>>(pos);

    const int smem = (16 * ANR + 8 * 49) * (int)sizeof(float4); // 56,448 B
    cudaFuncSetAttribute(attn_kernel, cudaFuncAttributeMaxDynamicSharedMemorySize, smem);
    attn_kernel<<<dim3(64, Hd, Bd), 128, smem>>>(pos);

    out_kernel<<<dim3(Cd / BN, NPIX / BM, 1), 256>>>((float*)d_out);
}

// round 15
// speedup vs baseline: 1.4029x; 1.3146x over previous
#include <cuda_runtime.h>
#include <cuda_bf16.h>
#include <cstdint>

// Problem constants
#define Bd 4
#define Cd 256
#define Hd 8
#define NPIX 16384

// f32 intermediates
__device__ float g_Q[NPIX*Cd];
__device__ float g_K[NPIX*Cd];
__device__ float g_V[NPIX*Cd];

// split-bf16 operands
__device__ unsigned short g_Xhi[NPIX*Cd];
__device__ unsigned short g_Xlo[NPIX*Cd];
__device__ unsigned short g_AThi[NPIX*Cd];
__device__ unsigned short g_ATlo[NPIX*Cd];
__device__ unsigned short g_Wthi[4*Cd*Cd];     // W^T  [mat][n][k]
__device__ unsigned short g_Wtlo[4*Cd*Cd];

// ---------------------------------------------------------------------------
__device__ __forceinline__ void split1(float f, unsigned short& h, unsigned short& l) {
    __nv_bfloat16 hb = __float2bfloat16_rn(f);
    __nv_bfloat16 lb = __float2bfloat16_rn(f - __bfloat162float(hb));
    h = __bfloat16_as_ushort(hb);
    l = __bfloat16_as_ushort(lb);
}

__global__ void prep_x_kernel(const float* __restrict__ X)
{
    int g = blockIdx.x * blockDim.x + threadIdx.x;
    int e = g << 2;
    const float4 v = *(const float4*)(X + e);
    ushort4 h, l;
    split1(v.x, h.x, l.x); split1(v.y, h.y, l.y);
    split1(v.z, h.z, l.z); split1(v.w, h.w, l.w);
    *(ushort4*)(g_Xhi + e) = h;
    *(ushort4*)(g_Xlo + e) = l;
}

__global__ void prep_w_kernel(const float* __restrict__ Wq,
                              const float* __restrict__ Wk,
                              const float* __restrict__ Wv,
                              const float* __restrict__ Wo)
{
    int g = blockIdx.x * blockDim.x + threadIdx.x;   // 4*256*64
    int mat = g >> 14;
    int rem = g & 16383;
    int n   = rem >> 6;
    int k0  = (rem & 63) << 2;
    const float* W = (mat == 0) ? Wq : (mat == 1) ? Wk : (mat == 2) ? Wv : Wo;
    ushort4 h, l;
    split1(W[(size_t)(k0 + 0) * 256 + n], h.x, l.x);
    split1(W[(size_t)(k0 + 1) * 256 + n], h.y, l.y);
    split1(W[(size_t)(k0 + 2) * 256 + n], h.z, l.z);
    split1(W[(size_t)(k0 + 3) * 256 + n], h.w, l.w);
    int base = (((mat << 8) | n) << 8) + k0;
    *(ushort4*)(g_Wthi + base) = h;
    *(ushort4*)(g_Wtlo + base) = l;
}

// ---------------------------------------------------------------------------
// bf16 mma.sync GEMM, split trick restructured: 8 physical K-stages, each
// holding Ahi/Alo/Bhi/Blo tiles; 3 phase-groups per stage (hh, lh, hl).
// CTA 128x64, 256 threads (8 warps, 4m x 2n), warp tile 32x32.
// Dynamic smem: 61,440 B (double-buffered 4 tiles).
// ---------------------------------------------------------------------------
#define BM 128
#define BN 64
#define SSTR 40       // shorts per smem row (32 data + 8 pad)
#define A_SZ (BM*SSTR)          // 5120 shorts
#define B_SZ (BN*SSTR)          // 2560 shorts
#define OFF_AH 0
#define OFF_AL (2*A_SZ)
#define OFF_BH (4*A_SZ)
#define OFF_BL (4*A_SZ + 2*B_SZ)
#define SMEM_SHORTS (4*A_SZ + 4*B_SZ)   // 30720 shorts = 61440 B

__device__ __forceinline__ uint32_t smem_u32(const void* p) {
    uint32_t a;
    asm("{ .reg .u64 t; cvta.to.shared.u64 t, %1; cvt.u32.u64 %0, t; }" : "=r"(a) : "l"(p));
    return a;
}
__device__ __forceinline__ void ldsm_x4(uint32_t addr, unsigned& r0, unsigned& r1,
                                        unsigned& r2, unsigned& r3) {
    asm volatile("ldmatrix.sync.aligned.m8n8.x4.shared.b16 {%0,%1,%2,%3}, [%4];"
                 : "=r"(r0), "=r"(r1), "=r"(r2), "=r"(r3) : "r"(addr));
}
__device__ __forceinline__ void mma16816(float c[4], const unsigned a[4], const unsigned b[2]) {
    asm volatile(
        "mma.sync.aligned.m16n8k16.row.col.f32.bf16.bf16.f32 "
        "{%0,%1,%2,%3}, {%4,%5,%6,%7}, {%8,%9}, {%0,%1,%2,%3};"
        : "+f"(c[0]), "+f"(c[1]), "+f"(c[2]), "+f"(c[3])
        : "r"(a[0]), "r"(a[1]), "r"(a[2]), "r"(a[3]), "r"(b[0]), "r"(b[1]));
}

__device__ __forceinline__ void mma_gemm(const unsigned short* __restrict__ Ahi,
                                         const unsigned short* __restrict__ Alo,
                                         const unsigned short* __restrict__ Bhi,
                                         const unsigned short* __restrict__ Blo,
                                         float* __restrict__ C,
                                         const float* __restrict__ pos,
                                         bool addpos)
{
    extern __shared__ unsigned short sh[];

    const int t    = threadIdx.x;
    const int m0   = blockIdx.y * BM;
    const int n0   = blockIdx.x * BN;
    const int wid  = t >> 5;
    const int lane = t & 31;
    const int grp  = lane >> 2;
    const int tig  = lane & 3;
    const int wm0  = (wid >> 1) << 5;
    const int wn0  = (wid & 1) << 5;

    const int arow = t >> 1;           // 0..127
    const int aseg = (t & 1) << 4;     // 0 / 16
    const int brow = t >> 2;           // 0..63
    const int bseg = (t & 3) << 3;     // 0,8,16,24

    const uint32_t sb = smem_u32(sh);
    const int rA = lane & 15;
    const int cA = (lane >> 4) << 3;
    const int rB = ((lane >> 4) << 3) + (lane & 7);
    const int cB = ((lane >> 3) & 1) << 3;

    uint4 rah0, rah1, ral0, ral1, rbh, rbl;
    auto ldg = [&](int kk) {
        const size_t ab = (size_t)(m0 + arow) * 256 + (kk << 5) + aseg;
        rah0 = *(const uint4*)(Ahi + ab);
        rah1 = *(const uint4*)(Ahi + ab + 8);
        ral0 = *(const uint4*)(Alo + ab);
        ral1 = *(const uint4*)(Alo + ab + 8);
        const size_t bb = (size_t)(n0 + brow) * 256 + (kk << 5) + bseg;
        rbh = *(const uint4*)(Bhi + bb);
        rbl = *(const uint4*)(Blo + bb);
    };
    auto sts = [&](int buf) {
        const int ao = arow * SSTR + aseg;
        const int bo = brow * SSTR + bseg;
        *(uint4*)(&sh[OFF_AH + buf * A_SZ + ao])     = rah0;
        *(uint4*)(&sh[OFF_AH + buf * A_SZ + ao + 8]) = rah1;
        *(uint4*)(&sh[OFF_AL + buf * A_SZ + ao])     = ral0;
        *(uint4*)(&sh[OFF_AL + buf * A_SZ + ao + 8]) = ral1;
        *(uint4*)(&sh[OFF_BH + buf * B_SZ + bo])     = rbh;
        *(uint4*)(&sh[OFF_BL + buf * B_SZ + bo])     = rbl;
    };

    float acc[2][4][4];
#pragma unroll
    for (int mi = 0; mi < 2; mi++)
#pragma unroll
        for (int ni = 0; ni < 4; ni++)
#pragma unroll
            for (int j = 0; j < 4; j++) acc[mi][ni][j] = 0.f;

    ldg(0); sts(0); __syncthreads();

    for (int kk = 0; kk < 8; kk++) {
        const int buf = kk & 1;
        const bool more = (kk < 7);
        if (more) ldg(kk + 1);

        const uint32_t ahb = sb + (uint32_t)(OFF_AH + buf * A_SZ) * 2;
        const uint32_t alb = sb + (uint32_t)(OFF_AL + buf * A_SZ) * 2;
        const uint32_t bhb = sb + (uint32_t)(OFF_BH + buf * B_SZ) * 2;
        const uint32_t blb = sb + (uint32_t)(OFF_BL + buf * B_SZ) * 2;

        unsigned auh[2][2][4], aul[2][2][4], bub[4][2][2];

        // Ahi + Bhi fragments
#pragma unroll
        for (int kq = 0; kq < 2; kq++) {
#pragma unroll
            for (int mi = 0; mi < 2; mi++)
                ldsm_x4(ahb + (uint32_t)(((wm0 + mi * 16 + rA) * SSTR + kq * 16 + cA) * 2),
                        auh[mi][kq][0], auh[mi][kq][1], auh[mi][kq][2], auh[mi][kq][3]);
#pragma unroll
            for (int np = 0; np < 2; np++)
                ldsm_x4(bhb + (uint32_t)(((wn0 + np * 16 + rB) * SSTR + kq * 16 + cB) * 2),
                        bub[np * 2][kq][0], bub[np * 2][kq][1],
                        bub[np * 2 + 1][kq][0], bub[np * 2 + 1][kq][1]);
        }
        // Phase hh: Ahi * Bhi
#pragma unroll
        for (int kq = 0; kq < 2; kq++)
#pragma unroll
            for (int mi = 0; mi < 2; mi++)
#pragma unroll
                for (int ni = 0; ni < 4; ni++)
                    mma16816(acc[mi][ni], auh[mi][kq], bub[ni][kq]);

        // Alo fragments; phase lh: Alo * Bhi
#pragma unroll
        for (int kq = 0; kq < 2; kq++)
#pragma unroll
            for (int mi = 0; mi < 2; mi++)
                ldsm_x4(alb + (uint32_t)(((wm0 + mi * 16 + rA) * SSTR + kq * 16 + cA) * 2),
                        aul[mi][kq][0], aul[mi][kq][1], aul[mi][kq][2], aul[mi][kq][3]);
#pragma unroll
        for (int kq = 0; kq < 2; kq++)
#pragma unroll
            for (int mi = 0; mi < 2; mi++)
#pragma unroll
                for (int ni = 0; ni < 4; ni++)
                    mma16816(acc[mi][ni], aul[mi][kq], bub[ni][kq]);

        // Blo fragments (overwrite bub); phase hl: Ahi * Blo
#pragma unroll
        for (int kq = 0; kq < 2; kq++)
#pragma unroll
            for (int np = 0; np < 2; np++)
                ldsm_x4(blb + (uint32_t)(((wn0 + np * 16 + rB) * SSTR + kq * 16 + cB) * 2),
                        bub[np * 2][kq][0], bub[np * 2][kq][1],
                        bub[np * 2 + 1][kq][0], bub[np * 2 + 1][kq][1]);
#pragma unroll
        for (int kq = 0; kq < 2; kq++)
#pragma unroll
            for (int mi = 0; mi < 2; mi++)
#pragma unroll
                for (int ni = 0; ni < 4; ni++)
                    mma16816(acc[mi][ni], auh[mi][kq], bub[ni][kq]);

        if (more) { sts(buf ^ 1); __syncthreads(); }
    }

#pragma unroll
    for (int mi = 0; mi < 2; mi++) {
#pragma unroll
        for (int half = 0; half < 2; half++) {
            const int m = m0 + wm0 + mi * 16 + grp + half * 8;
            const float* pe = nullptr;
            if (addpos) {
                int y  = (m >> 6) & 63;
                int x  = m & 63;
                int qy = y - min(max(y, 3), 60) + 3;
                int qx = x - min(max(x, 3), 60) + 3;
                pe = pos + (size_t)(qy * 7 + qx) * 256;
            }
#pragma unroll
            for (int ni = 0; ni < 4; ni++) {
                const int n = n0 + wn0 + ni * 8 + tig * 2;
                float2 v = make_float2(acc[mi][ni][half * 2], acc[mi][ni][half * 2 + 1]);
                if (addpos) {
                    const float2 p = *(const float2*)(pe + n);
                    v.x += p.x; v.y += p.y;
                }
                *(float2*)(C + (size_t)m * 256 + n) = v;
            }
        }
    }
}

__global__ __launch_bounds__(256) void qkv_kernel(const float* __restrict__ pos)
{
    const int mat = blockIdx.z;
    float* C = (mat == 0) ? g_Q : (mat == 1) ? g_K : g_V;
    mma_gemm(g_Xhi, g_Xlo,
             g_Wthi + (size_t)mat * 65536, g_Wtlo + (size_t)mat * 65536,
             C, pos, mat == 0);
}

__global__ __launch_bounds__(256) void out_kernel(float* __restrict__ out)
{
    mma_gemm(g_AThi, g_ATlo,
             g_Wthi + (size_t)3 * 65536, g_Wtlo + (size_t)3 * 65536,
             out, nullptr, false);
}

// ---------------------------------------------------------------------------
// Attention (R13-proven): single pass, lane-pair feature split, 8x8 tile.
// ---------------------------------------------------------------------------
#define AHW 14
#define ANR (AHW*AHW)   // 196

__global__ __launch_bounds__(128, 4) void attn_kernel(const float* __restrict__ pos)
{
    extern __shared__ float4 sm4[];
    float4* Ks4 = sm4;                  // [8][ANR]
    float4* Vs4 = sm4 + 8 * ANR;        // [8][ANR]
    float4* Ps4 = sm4 + 16 * ANR;       // [8][49]

    const int bx = blockIdx.x;          // 0..63
    const int h  = blockIdx.y;
    const int b  = blockIdx.z;
    const int Ty = (bx >> 3) << 3;
    const int Tx = (bx & 7) << 3;
    const int t  = threadIdx.x;
    const int hb = h * 32;

    for (int i = t; i < ANR * 8; i += 128) {
        int r  = i >> 3;
        int f4 = i & 7;
        int ry = r / AHW;
        int rx = r - ry * AHW;
        int gy = min(max(Ty - 3 + ry, 0), 63);
        int gx = min(max(Tx - 3 + rx, 0), 63);
        size_t off = ((size_t)(((b << 6) + gy) << 6) + gx) * 256 + hb + (f4 << 2);
        Ks4[f4 * ANR + r] = *(const float4*)(g_K + off);
        Vs4[f4 * ANR + r] = *(const float4*)(g_V + off);
    }
    for (int i = t; i < 49 * 8; i += 128) {
        int s  = i >> 3;
        int f4 = i & 7;
        Ps4[f4 * 49 + s] = *(const float4*)(pos + (size_t)s * 256 + hb + (f4 << 2));
    }
    __syncthreads();

    const int warp = t >> 5;
    const int lane = t & 31;
    const int half = lane >> 4;
    const int pix  = (warp << 4) + (lane & 15);
    const int f4b  = half << 2;

    const int py = pix >> 3, px = pix & 7;
    const int gy = Ty + py, gx = Tx + px;
    const int pr0 = min(max(gy, 3), 60) - Ty;
    const int pc0 = min(max(gx, 3), 60) - Tx;
    const size_t gp = ((size_t)(((b << 6) + gy) << 6) + gx) * 256 + hb;

    const float scale = 0.17677669529663687f;
    float4 q[4];
#pragma unroll
    for (int j = 0; j < 4; j++) {
        float4 v = *(const float4*)(g_Q + gp + ((f4b + j) << 2));
        v.x *= scale; v.y *= scale; v.z *= scale; v.w *= scale;
        q[j] = v;
    }

    float l = 0.f;
    float4 acc[4];
#pragma unroll
    for (int j = 0; j < 4; j++) acc[j] = make_float4(0.f, 0.f, 0.f, 0.f);

#pragma unroll 1
    for (int dy = 0; dy < 7; dy++) {
        const int r0 = (pr0 + dy) * AHW + pc0;
        const int s0 = dy * 7;
#pragma unroll
        for (int dx = 0; dx < 7; dx++) {
            const int r = r0 + dx;
            const int s = s0 + dx;
            float4 d = make_float4(0.f, 0.f, 0.f, 0.f);
#pragma unroll
            for (int j = 0; j < 4; j++) {
                const float4 k = Ks4[(f4b + j) * ANR + r];
                const float4 p = Ps4[(f4b + j) * 49 + s];
                d.x = fmaf(q[j].x, k.x + p.x, d.x);
                d.y = fmaf(q[j].y, k.y + p.y, d.y);
                d.z = fmaf(q[j].z, k.z + p.z, d.z);
                d.w = fmaf(q[j].w, k.w + p.w, d.w);
            }
            float part = (d.x + d.y) + (d.z + d.w);
            part += __shfl_xor_sync(0xffffffffu, part, 16);
            const float w = __expf(part);
            l += w;
#pragma unroll
            for (int j = 0; j < 4; j++) {
                const float4 v = Vs4[(f4b + j) * ANR + r];
                acc[j].x = fmaf(w, v.x, acc[j].x);
                acc[j].y = fmaf(w, v.y, acc[j].y);
                acc[j].z = fmaf(w, v.z, acc[j].z);
                acc[j].w = fmaf(w, v.w, acc[j].w);
            }
        }
    }

    const float inv = __fdividef(1.f, l + 1e-8f);
#pragma unroll
    for (int j = 0; j < 4; j++) {
        float o[4] = {acc[j].x * inv, acc[j].y * inv, acc[j].z * inv, acc[j].w * inv};
        ushort4 hv, lv;
        split1(o[0], hv.x, lv.x); split1(o[1], hv.y, lv.y);
        split1(o[2], hv.z, lv.z); split1(o[3], hv.w, lv.w);
        *(ushort4*)(g_AThi + gp + ((f4b + j) << 2)) = hv;
        *(ushort4*)(g_ATlo + gp + ((f4b + j) << 2)) = lv;
    }
}

// ---------------------------------------------------------------------------
extern "C" void kernel_launch(void* const* d_in, const int* in_sizes, int n_in,
                              void* d_out, int out_size)
{
    const float* x   = (const float*)d_in[0];
    const float* Wq  = (const float*)d_in[1];
    const float* Wk  = (const float*)d_in[2];
    const float* Wv  = (const float*)d_in[3];
    const float* Wo  = (const float*)d_in[4];
    const float* pos = (const float*)d_in[5];

    prep_w_kernel<<<256, 256>>>(Wq, Wk, Wv, Wo);
    prep_x_kernel<<<4096, 256>>>(x);

    const int gsmem = SMEM_SHORTS * 2;   // 61,440 B
    cudaFuncSetAttribute(qkv_kernel, cudaFuncAttributeMaxDynamicSharedMemorySize, gsmem);
    cudaFuncSetAttribute(out_kernel, cudaFuncAttributeMaxDynamicSharedMemorySize, gsmem);

    qkv_kernel<<<dim3(Cd / BN, NPIX / BM, 3), 256, gsmem>>>(pos);

    const int asmem = (16 * ANR + 8 * 49) * (int)sizeof(float4); // 56,448 B
    cudaFuncSetAttribute(attn_kernel, cudaFuncAttributeMaxDynamicSharedMemorySize, asmem);
    attn_kernel<<<dim3(64, Hd, Bd), 128, asmem>>>(pos);

    out_kernel<<<dim3(Cd / BN, NPIX / BM, 1), 256, gsmem>>>((float*)d_out);
}